// round 5
// baseline (speedup 1.0000x reference)
#include <cuda_runtime.h>
#include <math_constants.h>

#define B    32
#define C    256
#define HW   4096          // 64*64
#define HID  16
#define CHB  8             // batches per chunk (33.5 MB < 126 MB L2)
#define NCH  (B/CHB)       // 4 chunks
#define NCTA 256           // <= 2 CTAs/SM on 148 SMs -> guaranteed co-resident
#define NUNITS 512         // work units per phase (grid-strided)

// scratch (__device__ globals; allocation-free rule)
__device__ float  g_avg [B*C];
__device__ float  g_max [B*C];
__device__ float  g_catt[B*C];
__device__ float4 g_spavg4[B*1024];
__device__ float4 g_spmax4[B*1024];
__device__ unsigned g_barc[2*NCH];   // monotonic ticket counters (replay-safe)

__device__ __forceinline__ float sigmoidf(float v) { return 1.f / (1.f + __expf(-v)); }

// ticket-based grid barrier: wrap-safe, monotonic (no reset across graph replays)
__device__ __forceinline__ void gridbar(int id) {
    __syncthreads();
    if (threadIdx.x == 0) {
        __threadfence();
        unsigned t = atomicAdd(&g_barc[id], 1u);
        unsigned target = t - (t % NCTA) + NCTA;
        while ((int)(*(volatile unsigned*)&g_barc[id] - target) < 0)
            __nanosleep(64);
        __threadfence();
    }
    __syncthreads();
}

__global__ void __launch_bounds__(256, 2)
k_persist(const float* __restrict__ x,
          const float* __restrict__ w1, const float* __restrict__ w2,
          const float* __restrict__ w_sp, float* __restrict__ out)
{
    const int tid = threadIdx.x;
    const int cta = blockIdx.x;

    // --- shared memory (~22 KB total) ---
    __shared__ float ss[8], sm[8];                         // P1
    __shared__ float s_avg[C], s_mx[C], s_h[HID], sc[C];   // P2
    __shared__ float4 rs[16][16], rm[16][16];              // P2 reduce
    __shared__ float s_w[98];                              // P3 weights
    __shared__ float sp[2][14 * 72];                       // P3 padded tile
    __shared__ __align__(16) float s_att[512];             // P3 conv out (8x64)
    __shared__ float s_c[32];                              // P3 catt slice

    for (int chk = 0; chk < NCH; chk++) {
        const int b0 = chk * CHB;

        // ================= P1: channel mean/max (cold read of chunk) =======
        for (int p = cta; p < CHB * C; p += NCTA) {
            int plane = b0 * C + p;
            const float4* xp = (const float4*)x + (size_t)plane * 1024;
            float s = 0.f, m = -CUDART_INF_F;
#pragma unroll
            for (int k = 0; k < 4; k++) {
                float4 v = xp[k * 256 + tid];
                s += (v.x + v.y) + (v.z + v.w);
                m = fmaxf(m, fmaxf(fmaxf(v.x, v.y), fmaxf(v.z, v.w)));
            }
#pragma unroll
            for (int off = 16; off; off >>= 1) {
                s += __shfl_down_sync(0xffffffffu, s, off);
                m = fmaxf(m, __shfl_down_sync(0xffffffffu, m, off));
            }
            if ((tid & 31) == 0) { ss[tid >> 5] = s; sm[tid >> 5] = m; }
            __syncthreads();
            if (tid == 0) {
                float S = 0.f, M = -CUDART_INF_F;
#pragma unroll
                for (int i = 0; i < 8; i++) { S += ss[i]; M = fmaxf(M, sm[i]); }
                g_avg[plane] = S * (1.f / 4096.f);
                g_max[plane] = M;
            }
            __syncthreads();
        }
        gridbar(2 * chk);

        // ================= P2: MLP (redundant) + spatial stats (L2-hot) ====
        for (int unit = cta; unit < NUNITS; unit += NCTA) {
            const int b = b0 + (unit >> 6);
            const int g = unit & 63;                // 64 groups of 16 float4

            s_avg[tid] = __ldcg(&g_avg[b * C + tid]);
            s_mx [tid] = __ldcg(&g_max[b * C + tid]);
            __syncthreads();

            {   // hidden layer: 16 units x 16-lane dot
                int r = tid >> 4, l16 = tid & 15;
                float pa = 0.f, pm = 0.f;
#pragma unroll
                for (int j = 0; j < 16; j++) {
                    int c = l16 + j * 16;
                    float w = w1[r * C + c];
                    pa += w * s_avg[c];
                    pm += w * s_mx[c];
                }
#pragma unroll
                for (int off = 8; off; off >>= 1) {
                    pa += __shfl_down_sync(0xffffffffu, pa, off, 16);
                    pm += __shfl_down_sync(0xffffffffu, pm, off, 16);
                }
                if (l16 == 0) s_h[r] = fmaxf(pa, 0.f) + fmaxf(pm, 0.f);
            }
            __syncthreads();
            {
                float acc = 0.f;
#pragma unroll
                for (int rr = 0; rr < HID; rr++) acc += s_h[rr] * w2[tid * HID + rr];
                float catt = sigmoidf(acc);
                sc[tid] = catt;
                if (g == 0) g_catt[b * C + tid] = catt;
            }
            __syncthreads();

            const int px = tid & 15;                // float4 pixel in group
            const int cs = tid >> 4;                // channel split 0..15
            const float4* xp = (const float4*)x + ((size_t)(b * C) << 10) + g * 16 + px;
            float4 s = make_float4(0.f, 0.f, 0.f, 0.f);
            float4 m = make_float4(-CUDART_INF_F, -CUDART_INF_F, -CUDART_INF_F, -CUDART_INF_F);
#pragma unroll 4
            for (int j = 0; j < 16; j++) {
                int c    = cs * 16 + j;
                float a  = sc[c];
                float4 v = xp[(size_t)c * 1024];
                float vx = v.x * a, vy = v.y * a, vz = v.z * a, vw = v.w * a;
                s.x += vx; s.y += vy; s.z += vz; s.w += vw;
                m.x = fmaxf(m.x, vx); m.y = fmaxf(m.y, vy);
                m.z = fmaxf(m.z, vz); m.w = fmaxf(m.w, vw);
            }
            rs[cs][px] = s; rm[cs][px] = m;
            __syncthreads();
            if (tid < 16) {
                float4 S = rs[0][tid], M = rm[0][tid];
#pragma unroll
                for (int i = 1; i < 16; i++) {
                    float4 a4 = rs[i][tid], b4 = rm[i][tid];
                    S.x += a4.x; S.y += a4.y; S.z += a4.z; S.w += a4.w;
                    M.x = fmaxf(M.x, b4.x); M.y = fmaxf(M.y, b4.y);
                    M.z = fmaxf(M.z, b4.z); M.w = fmaxf(M.w, b4.w);
                }
                const float inv = 1.f / (float)C;
                S.x *= inv; S.y *= inv; S.z *= inv; S.w *= inv;
                g_spavg4[b * 1024 + g * 16 + tid] = S;
                g_spmax4[b * 1024 + g * 16 + tid] = M;
            }
            __syncthreads();
        }
        gridbar(2 * chk + 1);

        // ================= P3: 7x7 conv + sigmoid + apply (L2-hot) =========
        for (int unit = cta; unit < NUNITS; unit += NCTA) {
            const int b    = b0 + (unit >> 6);
            const int rest = unit & 63;
            const int band = rest >> 3;             // 8 bands of 8 rows
            const int cg   = rest & 7;              // 8 groups of 32 channels
            const int h0   = band * 8;

            for (int i = tid; i < 98; i += 256) s_w[i] = w_sp[i];
            for (int i = tid; i < 2 * 14 * 72; i += 256) ((float*)sp)[i] = 0.f;
            if (tid < 32) s_c[tid] = __ldcg(&g_catt[b * C + cg * 32 + tid]);
            __syncthreads();

            const float* spavg = (const float*)g_spavg4;
            const float* spmax = (const float*)g_spmax4;
            for (int idx = tid; idx < 14 * 64; idx += 256) {
                int r  = idx >> 6;
                int cx = idx & 63;
                int gh = h0 + r - 3;
                if (gh >= 0 && gh < 64) {
                    sp[0][r * 72 + 3 + cx] = __ldcg(&spavg[b * HW + gh * 64 + cx]);
                    sp[1][r * 72 + 3 + cx] = __ldcg(&spmax[b * HW + gh * 64 + cx]);
                }
            }
            __syncthreads();

            // conv: 512 pixels, 2 per thread
#pragma unroll
            for (int t2 = 0; t2 < 2; t2++) {
                int t  = tid + t2 * 256;
                int hl = t >> 6;
                int wx = t & 63;
                float acc = 0.f;
#pragma unroll
                for (int i = 0; i < 2; i++)
#pragma unroll
                    for (int kh = 0; kh < 7; kh++) {
                        const float* row  = &sp[i][(hl + kh) * 72 + wx];
                        const float* wrow = &s_w[i * 49 + kh * 7];
#pragma unroll
                        for (int kw = 0; kw < 7; kw++)
                            acc += row[kw] * wrow[kw];
                    }
                s_att[t] = sigmoidf(acc);
            }
            __syncthreads();

            // apply: 32 channels x (8 rows x 16 f4); 2 channels in flight
            {
                const float4* s_att4 = (const float4*)s_att;
                int px   = tid & 127;               // f4 within 8x16 tile
                int half = tid >> 7;                // 0..1
                int row  = px >> 4, c4 = px & 15;
                float4 a4 = s_att4[row * 16 + c4];
                size_t base_px = (size_t)(h0 + row) * 16 + c4;
#pragma unroll 4
                for (int it = 0; it < 16; it++) {
                    int ci   = half + it * 2;
                    float ca = s_c[ci];
                    size_t idx = (((size_t)(b * C + cg * 32 + ci)) << 10) + base_px;
                    float4 v = ((const float4*)x)[idx];
                    float4 o;
                    o.x = v.x * ca * a4.x;
                    o.y = v.y * ca * a4.y;
                    o.z = v.z * ca * a4.z;
                    o.w = v.w * ca * a4.w;
                    __stcs((float4*)out + idx, o);
                }
            }
            __syncthreads();   // smem reused next unit/chunk
        }
    }
}

// ---------------------------------------------------------------------------
extern "C" void kernel_launch(void* const* d_in, const int* in_sizes, int n_in,
                              void* d_out, int out_size) {
    const float* x    = (const float*)d_in[0];   // [32,256,64,64]
    const float* w1   = (const float*)d_in[1];   // [16,256]
    const float* w2   = (const float*)d_in[2];   // [256,16]
    const float* w_sp = (const float*)d_in[3];   // [1,2,7,7]
    float* out = (float*)d_out;

    k_persist<<<NCTA, 256>>>(x, w1, w2, w_sp, out);
}

// round 6
// speedup vs baseline: 1.3137x; 1.3137x over previous
#include <cuda_runtime.h>
#include <cuda_fp16.h>
#include <math_constants.h>

#define B    32
#define C    256
#define HW   4096          // 64*64
#define HID  16

// scratch (__device__ globals; allocation-free rule)
__device__ __half2 g_x16[B*C*HW/2];      // 67 MB fp16 shadow of x
__device__ float   g_avg [B*C];
__device__ float   g_max [B*C];
__device__ float   g_catt[B*C];
__device__ float   g_spavg[B*HW];
__device__ float   g_spmax[B*HW];

__device__ __forceinline__ float sigmoidf(float v) { return 1.f / (1.f + __expf(-v)); }

// ---------------------------------------------------------------------------
// k1: channel mean/max (exact fp32) + write fp16 shadow.
// 8192 blocks x 256 thr. fp32 read is __ldcs (evict-first) so the fp16
// shadow (normal stores) owns L2 afterwards.
// ---------------------------------------------------------------------------
__global__ __launch_bounds__(256) void k1_stats_cvt(const float* __restrict__ x) {
    int plane = blockIdx.x;                     // b*C + c
    const float4* xp = (const float4*)x + (size_t)plane * 1024;
    uint2* sh = (uint2*)g_x16 + (size_t)plane * 1024;

    float s = 0.f, m = -CUDART_INF_F;
#pragma unroll
    for (int k = 0; k < 4; k++) {
        int i = k * 256 + threadIdx.x;
        float4 v = __ldcs(&xp[i]);
        s += (v.x + v.y) + (v.z + v.w);
        m = fmaxf(m, fmaxf(fmaxf(v.x, v.y), fmaxf(v.z, v.w)));
        __half2 h01 = __floats2half2_rn(v.x, v.y);
        __half2 h23 = __floats2half2_rn(v.z, v.w);
        uint2 u;
        u.x = *(unsigned*)&h01;
        u.y = *(unsigned*)&h23;
        sh[i] = u;                              // normal store -> stays in L2
    }
#pragma unroll
    for (int off = 16; off; off >>= 1) {
        s += __shfl_down_sync(0xffffffffu, s, off);
        m = fmaxf(m, __shfl_down_sync(0xffffffffu, m, off));
    }
    __shared__ float ss[8], sm[8];
    if ((threadIdx.x & 31) == 0) { ss[threadIdx.x >> 5] = s; sm[threadIdx.x >> 5] = m; }
    __syncthreads();
    if (threadIdx.x == 0) {
        float S = 0.f, M = -CUDART_INF_F;
#pragma unroll
        for (int i = 0; i < 8; i++) { S += ss[i]; M = fmaxf(M, sm[i]); }
        g_avg[plane] = S * (1.f / 4096.f);
        g_max[plane] = M;
    }
}

// ---------------------------------------------------------------------------
// k3: inline channel-MLP (redundant per block) + spatial mean/max of x16*catt.
// 1024 blocks x 256 thr. Block = (batch, group of 16 uint4 = 128 pixels);
// thread = (uint4-pos 0..15, channel-split 0..15 of 16 channels each).
// ---------------------------------------------------------------------------
__global__ __launch_bounds__(256) void k3_spstats(const float* __restrict__ w1,
                                                  const float* __restrict__ w2) {
    const int b   = blockIdx.x >> 5;
    const int g   = blockIdx.x & 31;
    const int tid = threadIdx.x;

    __shared__ float s_avg[C], s_mx[C], s_h[HID], sc[C];
    s_avg[tid] = g_avg[b * C + tid];
    s_mx [tid] = g_max[b * C + tid];
    __syncthreads();

    {   // hidden layer
        int r = tid >> 4, l16 = tid & 15;
        float pa = 0.f, pm = 0.f;
#pragma unroll
        for (int j = 0; j < 16; j++) {
            int c = l16 + j * 16;
            float w = w1[r * C + c];
            pa += w * s_avg[c];
            pm += w * s_mx[c];
        }
#pragma unroll
        for (int off = 8; off; off >>= 1) {
            pa += __shfl_down_sync(0xffffffffu, pa, off, 16);
            pm += __shfl_down_sync(0xffffffffu, pm, off, 16);
        }
        if (l16 == 0) s_h[r] = fmaxf(pa, 0.f) + fmaxf(pm, 0.f);
    }
    __syncthreads();
    {
        float acc = 0.f;
#pragma unroll
        for (int rr = 0; rr < HID; rr++) acc += s_h[rr] * w2[tid * HID + rr];
        float catt = sigmoidf(acc);
        sc[tid] = catt;
        if (g == 0) g_catt[b * C + tid] = catt;
    }
    __syncthreads();

    const int px = tid & 15;                // uint4 within group (8 pixels)
    const int cs = tid >> 4;                // channel split 0..15
    const uint4* xp = (const uint4*)g_x16 + (size_t)(b * C) * 512 + g * 16 + px;

    float s[8], m[8];
#pragma unroll
    for (int i = 0; i < 8; i++) { s[i] = 0.f; m[i] = -CUDART_INF_F; }

#pragma unroll 4
    for (int j = 0; j < 16; j++) {
        int c   = cs * 16 + j;
        float a = sc[c];
        uint4 u = xp[(size_t)c * 512];
        float2 f01 = __half22float2(*(__half2*)&u.x);
        float2 f23 = __half22float2(*(__half2*)&u.y);
        float2 f45 = __half22float2(*(__half2*)&u.z);
        float2 f67 = __half22float2(*(__half2*)&u.w);
        float v[8] = {f01.x, f01.y, f23.x, f23.y, f45.x, f45.y, f67.x, f67.y};
#pragma unroll
        for (int i = 0; i < 8; i++) {
            float t = v[i] * a;
            s[i] += t;
            m[i] = fmaxf(m[i], t);
        }
    }

    __shared__ float rsum[16][16][8];
    __shared__ float rmax[16][16][8];
#pragma unroll
    for (int i = 0; i < 8; i++) { rsum[cs][px][i] = s[i]; rmax[cs][px][i] = m[i]; }
    __syncthreads();

    // 128 threads: thread = (px 0..15, lane 0..7), reduce over 16 splits
    if (tid < 128) {
        int p = tid >> 3, lane = tid & 7;
        float S = rsum[0][p][lane], M = rmax[0][p][lane];
#pragma unroll
        for (int i = 1; i < 16; i++) {
            S += rsum[i][p][lane];
            M = fmaxf(M, rmax[i][p][lane]);
        }
        int pix = g * 128 + p * 8 + lane;
        g_spavg[b * HW + pix] = S * (1.f / (float)C);
        g_spmax[b * HW + pix] = M;
    }
}

// ---------------------------------------------------------------------------
// k5: inline 7x7 conv + sigmoid (redundant per channel-group) + final apply.
// 2048 blocks x 256 thr. Block = (batch, 8-row band, 32-channel group).
// Reads x16 (L2-warm), writes fp32 out with streaming stores.
// ---------------------------------------------------------------------------
__global__ __launch_bounds__(256) void k5_final(const float* __restrict__ w_sp,
                                                float* __restrict__ out) {
    const int b    = blockIdx.x >> 6;
    const int rest = blockIdx.x & 63;
    const int band = rest >> 3;             // 0..7 -> 8 rows each
    const int cg   = rest & 7;              // 0..7 -> 32 channels each
    const int h0   = band * 8;
    const int tid  = threadIdx.x;

    __shared__ float s_w[98];
    __shared__ float sp[2][14 * 72];
    __shared__ __align__(16) float s_att[512];
    __shared__ float s_c[32];

    for (int i = tid; i < 98; i += 256) s_w[i] = w_sp[i];
    for (int i = tid; i < 2 * 14 * 72; i += 256) ((float*)sp)[i] = 0.f;
    if (tid < 32) s_c[tid] = g_catt[b * C + cg * 32 + tid];
    __syncthreads();

    for (int idx = tid; idx < 14 * 64; idx += 256) {
        int r  = idx >> 6;
        int cx = idx & 63;
        int gh = h0 + r - 3;
        if (gh >= 0 && gh < 64) {
            sp[0][r * 72 + 3 + cx] = g_spavg[b * HW + gh * 64 + cx];
            sp[1][r * 72 + 3 + cx] = g_spmax[b * HW + gh * 64 + cx];
        }
    }
    __syncthreads();

    // conv: 512 tile pixels, 2 per thread
#pragma unroll
    for (int t2 = 0; t2 < 2; t2++) {
        int t  = tid + t2 * 256;
        int hl = t >> 6;
        int wx = t & 63;
        float acc = 0.f;
#pragma unroll
        for (int i = 0; i < 2; i++)
#pragma unroll
            for (int kh = 0; kh < 7; kh++) {
                const float* row  = &sp[i][(hl + kh) * 72 + wx];
                const float* wrow = &s_w[i * 49 + kh * 7];
#pragma unroll
                for (int kw = 0; kw < 7; kw++)
                    acc += row[kw] * wrow[kw];
            }
        s_att[t] = sigmoidf(acc);
    }
    __syncthreads();

    // apply: thread = (uint4-pos 0..63 within band, split 0..3 of 8 channels)
    {
        const int u4    = tid & 63;             // 8 consecutive pixels
        const int split = tid >> 6;             // 0..3
        const float4* a4p = (const float4*)s_att + u4 * 2;
        float4 aA = a4p[0], aB = a4p[1];

        const uint4* xbase = (const uint4*)g_x16
                           + (size_t)(b * C + cg * 32) * 512 + band * 64 + u4;
        float4* obase = (float4*)out
                      + ((size_t)(b * C + cg * 32) * 1024) + band * 128 + u4 * 2;

#pragma unroll 4
        for (int j = 0; j < 8; j++) {
            int ci   = split * 8 + j;
            float ca = s_c[ci];
            uint4 u  = xbase[(size_t)ci * 512];
            float2 f01 = __half22float2(*(__half2*)&u.x);
            float2 f23 = __half22float2(*(__half2*)&u.y);
            float2 f45 = __half22float2(*(__half2*)&u.z);
            float2 f67 = __half22float2(*(__half2*)&u.w);
            float4 oA, oB;
            oA.x = f01.x * ca * aA.x;
            oA.y = f01.y * ca * aA.y;
            oA.z = f23.x * ca * aA.z;
            oA.w = f23.y * ca * aA.w;
            oB.x = f45.x * ca * aB.x;
            oB.y = f45.y * ca * aB.y;
            oB.z = f67.x * ca * aB.z;
            oB.w = f67.y * ca * aB.w;
            __stcs(obase + (size_t)ci * 1024, oA);
            __stcs(obase + (size_t)ci * 1024 + 1, oB);
        }
    }
}

// ---------------------------------------------------------------------------
extern "C" void kernel_launch(void* const* d_in, const int* in_sizes, int n_in,
                              void* d_out, int out_size) {
    const float* x    = (const float*)d_in[0];   // [32,256,64,64]
    const float* w1   = (const float*)d_in[1];   // [16,256]
    const float* w2   = (const float*)d_in[2];   // [256,16]
    const float* w_sp = (const float*)d_in[3];   // [1,2,7,7]
    float* out = (float*)d_out;

    k1_stats_cvt<<<B * C, 256>>>(x);
    k3_spstats  <<<B * 32, 256>>>(w1, w2);
    k5_final    <<<B * 64, 256>>>(w_sp, out);
}

// round 7
// speedup vs baseline: 1.3220x; 1.0064x over previous
#include <cuda_runtime.h>
#include <cuda_fp16.h>
#include <math_constants.h>

#define B    32
#define C    256
#define HW   4096          // 64*64
#define HID  16

// scratch (__device__ globals; allocation-free rule)
__device__ __half2 g_x16[B*C*HW/2];      // 67 MB fp16 shadow of x
__device__ float   g_avg [B*C];
__device__ float   g_max [B*C];
__device__ float   g_catt[B*C];
__device__ float   g_spavg[B*HW];
__device__ float   g_spmax[B*HW];
__device__ float   g_att [B*HW];         // sigmoid(conv) result

__device__ __forceinline__ float sigmoidf(float v) { return 1.f / (1.f + __expf(-v)); }

// ---------------------------------------------------------------------------
// k1: channel mean/max (exact fp32) + write fp16 shadow. 8192 blocks x 256.
// fp32 read streams (__ldcs); fp16 shadow uses normal stores (L2-resident).
// ---------------------------------------------------------------------------
__global__ __launch_bounds__(256) void k1_stats_cvt(const float* __restrict__ x) {
    int plane = blockIdx.x;                     // b*C + c
    const float4* xp = (const float4*)x + (size_t)plane * 1024;
    uint2* sh = (uint2*)g_x16 + (size_t)plane * 1024;

    float s = 0.f, m = -CUDART_INF_F;
#pragma unroll
    for (int k = 0; k < 4; k++) {
        int i = k * 256 + threadIdx.x;
        float4 v = __ldcs(&xp[i]);
        s += (v.x + v.y) + (v.z + v.w);
        m = fmaxf(m, fmaxf(fmaxf(v.x, v.y), fmaxf(v.z, v.w)));
        __half2 h01 = __floats2half2_rn(v.x, v.y);
        __half2 h23 = __floats2half2_rn(v.z, v.w);
        uint2 u;
        u.x = *(unsigned*)&h01;
        u.y = *(unsigned*)&h23;
        sh[i] = u;
    }
#pragma unroll
    for (int off = 16; off; off >>= 1) {
        s += __shfl_down_sync(0xffffffffu, s, off);
        m = fmaxf(m, __shfl_down_sync(0xffffffffu, m, off));
    }
    __shared__ float ss[8], sm[8];
    if ((threadIdx.x & 31) == 0) { ss[threadIdx.x >> 5] = s; sm[threadIdx.x >> 5] = m; }
    __syncthreads();
    if (threadIdx.x == 0) {
        float S = 0.f, M = -CUDART_INF_F;
#pragma unroll
        for (int i = 0; i < 8; i++) { S += ss[i]; M = fmaxf(M, sm[i]); }
        g_avg[plane] = S * (1.f / 4096.f);
        g_max[plane] = M;
    }
}

// ---------------------------------------------------------------------------
// k3: inline channel-MLP (redundant per block) + spatial mean/max of x16*catt.
// 2048 blocks x 256 thr. Block = (batch, group of 8 uint4 = 64 pixels);
// thread = (u4 0..7, split 0..31 of 8 channels). Only 8 loads per thread.
// ---------------------------------------------------------------------------
__global__ __launch_bounds__(256) void k3_spstats(const float* __restrict__ w1,
                                                  const float* __restrict__ w2) {
    const int b   = blockIdx.x >> 6;
    const int g   = blockIdx.x & 63;            // 64 groups of 64 px
    const int tid = threadIdx.x;

    __shared__ float s_avg[C], s_mx[C], s_h[HID], sc[C];
    s_avg[tid] = g_avg[b * C + tid];
    s_mx [tid] = g_max[b * C + tid];
    __syncthreads();

    {   // hidden layer: 16 units x 16-lane dot
        int r = tid >> 4, l16 = tid & 15;
        float pa = 0.f, pm = 0.f;
#pragma unroll
        for (int j = 0; j < 16; j++) {
            int c = l16 + j * 16;
            float w = w1[r * C + c];
            pa += w * s_avg[c];
            pm += w * s_mx[c];
        }
#pragma unroll
        for (int off = 8; off; off >>= 1) {
            pa += __shfl_down_sync(0xffffffffu, pa, off, 16);
            pm += __shfl_down_sync(0xffffffffu, pm, off, 16);
        }
        if (l16 == 0) s_h[r] = fmaxf(pa, 0.f) + fmaxf(pm, 0.f);
    }
    __syncthreads();
    {
        float acc = 0.f;
#pragma unroll
        for (int rr = 0; rr < HID; rr++) acc += s_h[rr] * w2[tid * HID + rr];
        float catt = sigmoidf(acc);
        sc[tid] = catt;
        if (g == 0) g_catt[b * C + tid] = catt;
    }
    __syncthreads();

    const int u4    = tid & 7;              // uint4 in group (8 px each)
    const int split = tid >> 3;             // 0..31, 8 channels each
    const uint4* xp = (const uint4*)g_x16 + (size_t)(b * C) * 512 + g * 8 + u4;

    float s[8], m[8];
#pragma unroll
    for (int i = 0; i < 8; i++) { s[i] = 0.f; m[i] = -CUDART_INF_F; }

#pragma unroll
    for (int j = 0; j < 8; j++) {
        int c   = split * 8 + j;
        float a = sc[c];
        uint4 u = xp[(size_t)c * 512];
        float2 f01 = __half22float2(*(__half2*)&u.x);
        float2 f23 = __half22float2(*(__half2*)&u.y);
        float2 f45 = __half22float2(*(__half2*)&u.z);
        float2 f67 = __half22float2(*(__half2*)&u.w);
        float v[8] = {f01.x, f01.y, f23.x, f23.y, f45.x, f45.y, f67.x, f67.y};
#pragma unroll
        for (int i = 0; i < 8; i++) {
            float t = v[i] * a;
            s[i] += t;
            m[i] = fmaxf(m[i], t);
        }
    }

    __shared__ float rsum[32][8][8];
    __shared__ float rmax[32][8][8];
#pragma unroll
    for (int i = 0; i < 8; i++) { rsum[split][u4][i] = s[i]; rmax[split][u4][i] = m[i]; }
    __syncthreads();

    // 64 threads: thread = (u4 0..7, lane 0..7), reduce over 32 splits
    if (tid < 64) {
        int p = tid >> 3, lane = tid & 7;
        float S = rsum[0][p][lane], M = rmax[0][p][lane];
#pragma unroll
        for (int i = 1; i < 32; i++) {
            S += rsum[i][p][lane];
            M = fmaxf(M, rmax[i][p][lane]);
        }
        int pix = g * 64 + p * 8 + lane;
        g_spavg[b * HW + pix] = S * (1.f / (float)C);
        g_spmax[b * HW + pix] = M;
    }
}

// ---------------------------------------------------------------------------
// k4: 7x7 "same" conv over [spavg, spmax] + sigmoid -> g_att. Computed ONCE.
// 512 blocks (b x 16 bands of 4 rows) x 256 thr, 1 pixel/thread.
// ---------------------------------------------------------------------------
__global__ __launch_bounds__(256) void k4_conv(const float* __restrict__ w_sp) {
    const int b    = blockIdx.x >> 4;
    const int band = blockIdx.x & 15;
    const int h0   = band * 4;
    const int tid  = threadIdx.x;

    __shared__ float sp[2][10 * 72];            // rows h0-3..h0+6, col pad 3
    __shared__ float s_w[98];

    for (int i = tid; i < 98; i += 256) s_w[i] = w_sp[i];
    for (int i = tid; i < 2 * 10 * 72; i += 256) ((float*)sp)[i] = 0.f;
    __syncthreads();

    for (int idx = tid; idx < 10 * 64; idx += 256) {
        int r  = idx >> 6;
        int cx = idx & 63;
        int gh = h0 + r - 3;
        if (gh >= 0 && gh < 64) {
            sp[0][r * 72 + 3 + cx] = g_spavg[b * HW + gh * 64 + cx];
            sp[1][r * 72 + 3 + cx] = g_spmax[b * HW + gh * 64 + cx];
        }
    }
    __syncthreads();

    int hl = tid >> 6;      // 0..3
    int wx = tid & 63;
    float acc = 0.f;
#pragma unroll
    for (int i = 0; i < 2; i++)
#pragma unroll
        for (int kh = 0; kh < 7; kh++) {
            const float* row  = &sp[i][(hl + kh) * 72 + wx];
            const float* wrow = &s_w[i * 49 + kh * 7];
#pragma unroll
            for (int kw = 0; kw < 7; kw++)
                acc += row[kw] * wrow[kw];
        }
    g_att[b * HW + (h0 + hl) * 64 + wx] = sigmoidf(acc);
}

// ---------------------------------------------------------------------------
// k5: pure apply: out = x16 * catt * att. 2048 blocks x 256 thr.
// Block = (batch, 8-row band, 32-channel group). att/catt staged in smem.
// ---------------------------------------------------------------------------
__global__ __launch_bounds__(256) void k5_final(float* __restrict__ out) {
    const int b    = blockIdx.x >> 6;
    const int rest = blockIdx.x & 63;
    const int band = rest >> 3;             // 0..7 -> 8 rows each
    const int cg   = rest & 7;              // 0..7 -> 32 channels each
    const int tid  = threadIdx.x;

    __shared__ __align__(16) float s_att[512];
    __shared__ float s_c[32];

    s_att[tid]       = g_att[b * HW + band * 512 + tid];
    s_att[tid + 256] = g_att[b * HW + band * 512 + tid + 256];
    if (tid < 32) s_c[tid] = g_catt[b * C + cg * 32 + tid];
    __syncthreads();

    const int u4    = tid & 63;             // 8 consecutive pixels in band
    const int split = tid >> 6;             // 0..3
    const float4* a4p = (const float4*)s_att + u4 * 2;
    float4 aA = a4p[0], aB = a4p[1];

    const uint4* xbase = (const uint4*)g_x16
                       + (size_t)(b * C + cg * 32) * 512 + band * 64 + u4;
    float4* obase = (float4*)out
                  + ((size_t)(b * C + cg * 32) * 1024) + band * 128 + u4 * 2;

#pragma unroll 4
    for (int j = 0; j < 8; j++) {
        int ci   = split * 8 + j;
        float ca = s_c[ci];
        uint4 u  = xbase[(size_t)ci * 512];
        float2 f01 = __half22float2(*(__half2*)&u.x);
        float2 f23 = __half22float2(*(__half2*)&u.y);
        float2 f45 = __half22float2(*(__half2*)&u.z);
        float2 f67 = __half22float2(*(__half2*)&u.w);
        float4 oA, oB;
        oA.x = f01.x * ca * aA.x;
        oA.y = f01.y * ca * aA.y;
        oA.z = f23.x * ca * aA.z;
        oA.w = f23.y * ca * aA.w;
        oB.x = f45.x * ca * aB.x;
        oB.y = f45.y * ca * aB.y;
        oB.z = f67.x * ca * aB.z;
        oB.w = f67.y * ca * aB.w;
        __stcs(obase + (size_t)ci * 1024, oA);
        __stcs(obase + (size_t)ci * 1024 + 1, oB);
    }
}

// ---------------------------------------------------------------------------
extern "C" void kernel_launch(void* const* d_in, const int* in_sizes, int n_in,
                              void* d_out, int out_size) {
    const float* x    = (const float*)d_in[0];   // [32,256,64,64]
    const float* w1   = (const float*)d_in[1];   // [16,256]
    const float* w2   = (const float*)d_in[2];   // [256,16]
    const float* w_sp = (const float*)d_in[3];   // [1,2,7,7]
    float* out = (float*)d_out;

    k1_stats_cvt<<<B * C, 256>>>(x);
    k3_spstats  <<<B * 64, 256>>>(w1, w2);
    k4_conv     <<<B * 16, 256>>>(w_sp);
    k5_final    <<<B * 64, 256>>>(out);
}

// round 8
// speedup vs baseline: 1.5504x; 1.1727x over previous
#include <cuda_runtime.h>
#include <cuda_fp16.h>
#include <math_constants.h>

#define B    32
#define C    256
#define HW   4096          // 64*64
#define HID  16

// scratch (__device__ globals; allocation-free rule)
__device__ __half2 g_x16[B*C*HW/2];      // 67 MB fp16 shadow of x
__device__ float   g_avg [B*C];
__device__ float   g_max [B*C];
__device__ float   g_catt[B*C];
__device__ float   g_spavg[B*HW];
__device__ float   g_spmax[B*HW];
__device__ float   g_att [B*HW];         // sigmoid(conv) result

__device__ __forceinline__ float sigmoidf(float v) { return 1.f / (1.f + __expf(-v)); }

// ---------------------------------------------------------------------------
// k1: channel mean/max (exact fp32) + write fp16 shadow. 8192 blocks x 256.
// fp32 read streams (__ldcs); fp16 shadow uses normal stores (L2-resident).
// ---------------------------------------------------------------------------
__global__ __launch_bounds__(256) void k1_stats_cvt(const float* __restrict__ x) {
    int plane = blockIdx.x;                     // b*C + c
    const float4* xp = (const float4*)x + (size_t)plane * 1024;
    uint2* sh = (uint2*)g_x16 + (size_t)plane * 1024;

    float s = 0.f, m = -CUDART_INF_F;
#pragma unroll
    for (int k = 0; k < 4; k++) {
        int i = k * 256 + threadIdx.x;
        float4 v = __ldcs(&xp[i]);
        s += (v.x + v.y) + (v.z + v.w);
        m = fmaxf(m, fmaxf(fmaxf(v.x, v.y), fmaxf(v.z, v.w)));
        __half2 h01 = __floats2half2_rn(v.x, v.y);
        __half2 h23 = __floats2half2_rn(v.z, v.w);
        uint2 u;
        u.x = *(unsigned*)&h01;
        u.y = *(unsigned*)&h23;
        sh[i] = u;
    }
#pragma unroll
    for (int off = 16; off; off >>= 1) {
        s += __shfl_down_sync(0xffffffffu, s, off);
        m = fmaxf(m, __shfl_down_sync(0xffffffffu, m, off));
    }
    __shared__ float ss[8], sm[8];
    if ((threadIdx.x & 31) == 0) { ss[threadIdx.x >> 5] = s; sm[threadIdx.x >> 5] = m; }
    __syncthreads();
    if (threadIdx.x == 0) {
        float S = 0.f, M = -CUDART_INF_F;
#pragma unroll
        for (int i = 0; i < 8; i++) { S += ss[i]; M = fmaxf(M, sm[i]); }
        g_avg[plane] = S * (1.f / 4096.f);
        g_max[plane] = M;
    }
}

// ---------------------------------------------------------------------------
// k2: channel MLP + sigmoid -> g_catt. 32 blocks x 256 thr. Tiny.
// ---------------------------------------------------------------------------
__global__ __launch_bounds__(256) void k2_mlp(const float* __restrict__ w1,
                                              const float* __restrict__ w2) {
    int b   = blockIdx.x;
    int tid = threadIdx.x;
    __shared__ float s_avg[C], s_mx[C], s_h[HID];
    s_avg[tid] = g_avg[b * C + tid];
    s_mx [tid] = g_max[b * C + tid];
    __syncthreads();

    int r = tid >> 4, l16 = tid & 15;
    float pa = 0.f, pm = 0.f;
#pragma unroll
    for (int j = 0; j < 16; j++) {
        int c = l16 + j * 16;
        float w = w1[r * C + c];
        pa += w * s_avg[c];
        pm += w * s_mx[c];
    }
#pragma unroll
    for (int off = 8; off; off >>= 1) {
        pa += __shfl_down_sync(0xffffffffu, pa, off, 16);
        pm += __shfl_down_sync(0xffffffffu, pm, off, 16);
    }
    if (l16 == 0) s_h[r] = fmaxf(pa, 0.f) + fmaxf(pm, 0.f);
    __syncthreads();

    float acc = 0.f;
#pragma unroll
    for (int rr = 0; rr < HID; rr++) acc += s_h[rr] * w2[tid * HID + rr];
    g_catt[b * C + tid] = sigmoidf(acc);
}

// ---------------------------------------------------------------------------
// k3: spatial mean/max of x16*catt. 1024 blocks x 256 thr.
// Block = (batch, group of 16 uint4 = 128 px); thread = (u4 0..15,
// split 0..15 of 16 channels) -> 16 independent strided loads per thread.
// No MLP preamble (catt precomputed by k2).
// ---------------------------------------------------------------------------
__global__ __launch_bounds__(256) void k3_spstats() {
    const int b   = blockIdx.x >> 5;
    const int g   = blockIdx.x & 31;            // 32 groups of 128 px
    const int tid = threadIdx.x;

    __shared__ float sc[C];
    sc[tid] = g_catt[b * C + tid];
    __syncthreads();

    const int u4    = tid & 15;             // uint4 in group (8 px each)
    const int split = tid >> 4;             // 0..15, 16 channels each
    const uint4* xp = (const uint4*)g_x16 + (size_t)(b * C) * 512 + g * 16 + u4;

    float s[8], m[8];
#pragma unroll
    for (int i = 0; i < 8; i++) { s[i] = 0.f; m[i] = -CUDART_INF_F; }

#pragma unroll
    for (int j = 0; j < 16; j++) {
        int c   = split * 16 + j;
        float a = sc[c];
        uint4 u = xp[(size_t)c * 512];
        float2 f01 = __half22float2(*(__half2*)&u.x);
        float2 f23 = __half22float2(*(__half2*)&u.y);
        float2 f45 = __half22float2(*(__half2*)&u.z);
        float2 f67 = __half22float2(*(__half2*)&u.w);
        float v[8] = {f01.x, f01.y, f23.x, f23.y, f45.x, f45.y, f67.x, f67.y};
#pragma unroll
        for (int i = 0; i < 8; i++) {
            float t = v[i] * a;
            s[i] += t;
            m[i] = fmaxf(m[i], t);
        }
    }

    __shared__ float rsum[16][16][8];
    __shared__ float rmax[16][16][8];
#pragma unroll
    for (int i = 0; i < 8; i++) { rsum[split][u4][i] = s[i]; rmax[split][u4][i] = m[i]; }
    __syncthreads();

    // 128 threads: thread = (u4 0..15, lane 0..7), reduce over 16 splits
    if (tid < 128) {
        int p = tid >> 3, lane = tid & 7;
        float S = rsum[0][p][lane], M = rmax[0][p][lane];
#pragma unroll
        for (int i = 1; i < 16; i++) {
            S += rsum[i][p][lane];
            M = fmaxf(M, rmax[i][p][lane]);
        }
        int pix = g * 128 + p * 8 + lane;
        g_spavg[b * HW + pix] = S * (1.f / (float)C);
        g_spmax[b * HW + pix] = M;
    }
}

// ---------------------------------------------------------------------------
// k4: 7x7 "same" conv over [spavg, spmax] + sigmoid -> g_att. Computed ONCE.
// 512 blocks (b x 16 bands of 4 rows) x 256 thr, 1 pixel/thread.
// ---------------------------------------------------------------------------
__global__ __launch_bounds__(256) void k4_conv(const float* __restrict__ w_sp) {
    const int b    = blockIdx.x >> 4;
    const int band = blockIdx.x & 15;
    const int h0   = band * 4;
    const int tid  = threadIdx.x;

    __shared__ float sp[2][10 * 72];            // rows h0-3..h0+6, col pad 3
    __shared__ float s_w[98];

    for (int i = tid; i < 98; i += 256) s_w[i] = w_sp[i];
    for (int i = tid; i < 2 * 10 * 72; i += 256) ((float*)sp)[i] = 0.f;
    __syncthreads();

    for (int idx = tid; idx < 10 * 64; idx += 256) {
        int r  = idx >> 6;
        int cx = idx & 63;
        int gh = h0 + r - 3;
        if (gh >= 0 && gh < 64) {
            sp[0][r * 72 + 3 + cx] = g_spavg[b * HW + gh * 64 + cx];
            sp[1][r * 72 + 3 + cx] = g_spmax[b * HW + gh * 64 + cx];
        }
    }
    __syncthreads();

    int hl = tid >> 6;      // 0..3
    int wx = tid & 63;
    float acc = 0.f;
#pragma unroll
    for (int i = 0; i < 2; i++)
#pragma unroll
        for (int kh = 0; kh < 7; kh++) {
            const float* row  = &sp[i][(hl + kh) * 72 + wx];
            const float* wrow = &s_w[i * 49 + kh * 7];
#pragma unroll
            for (int kw = 0; kw < 7; kw++)
                acc += row[kw] * wrow[kw];
        }
    g_att[b * HW + (h0 + hl) * 64 + wx] = sigmoidf(acc);
}

// ---------------------------------------------------------------------------
// k5: pure apply: out = x16 * catt * att. 2048 blocks x 256 thr.
// Block = (batch, 8-row band, 32-channel group). att/catt staged in smem.
// ---------------------------------------------------------------------------
__global__ __launch_bounds__(256) void k5_final(float* __restrict__ out) {
    const int b    = blockIdx.x >> 6;
    const int rest = blockIdx.x & 63;
    const int band = rest >> 3;             // 0..7 -> 8 rows each
    const int cg   = rest & 7;              // 0..7 -> 32 channels each
    const int tid  = threadIdx.x;

    __shared__ __align__(16) float s_att[512];
    __shared__ float s_c[32];

    s_att[tid]       = g_att[b * HW + band * 512 + tid];
    s_att[tid + 256] = g_att[b * HW + band * 512 + tid + 256];
    if (tid < 32) s_c[tid] = g_catt[b * C + cg * 32 + tid];
    __syncthreads();

    const int u4    = tid & 63;             // 8 consecutive pixels in band
    const int split = tid >> 6;             // 0..3
    const float4* a4p = (const float4*)s_att + u4 * 2;
    float4 aA = a4p[0], aB = a4p[1];

    const uint4* xbase = (const uint4*)g_x16
                       + (size_t)(b * C + cg * 32) * 512 + band * 64 + u4;
    float4* obase = (float4*)out
                  + ((size_t)(b * C + cg * 32) * 1024) + band * 128 + u4 * 2;

#pragma unroll 4
    for (int j = 0; j < 8; j++) {
        int ci   = split * 8 + j;
        float ca = s_c[ci];
        uint4 u  = xbase[(size_t)ci * 512];
        float2 f01 = __half22float2(*(__half2*)&u.x);
        float2 f23 = __half22float2(*(__half2*)&u.y);
        float2 f45 = __half22float2(*(__half2*)&u.z);
        float2 f67 = __half22float2(*(__half2*)&u.w);
        float4 oA, oB;
        oA.x = f01.x * ca * aA.x;
        oA.y = f01.y * ca * aA.y;
        oA.z = f23.x * ca * aA.z;
        oA.w = f23.y * ca * aA.w;
        oB.x = f45.x * ca * aB.x;
        oB.y = f45.y * ca * aB.y;
        oB.z = f67.x * ca * aB.z;
        oB.w = f67.y * ca * aB.w;
        __stcs(obase + (size_t)ci * 1024, oA);
        __stcs(obase + (size_t)ci * 1024 + 1, oB);
    }
}

// ---------------------------------------------------------------------------
extern "C" void kernel_launch(void* const* d_in, const int* in_sizes, int n_in,
                              void* d_out, int out_size) {
    const float* x    = (const float*)d_in[0];   // [32,256,64,64]
    const float* w1   = (const float*)d_in[1];   // [16,256]
    const float* w2   = (const float*)d_in[2];   // [256,16]
    const float* w_sp = (const float*)d_in[3];   // [1,2,7,7]
    float* out = (float*)d_out;

    k1_stats_cvt<<<B * C, 256>>>(x);
    k2_mlp      <<<B, 256>>>(w1, w2);
    k3_spstats  <<<B * 32, 256>>>();
    k4_conv     <<<B * 16, 256>>>(w_sp);
    k5_final    <<<B * 64, 256>>>(out);
}